// round 1
// baseline (speedup 1.0000x reference)
#include <cuda_runtime.h>
#include <math.h>

#define D_DIM   10000
#define LVL     100
#define T_STEPS 2048
#define TERMS   2046          // T - 3 + 1
#define NCHUNK  28
#define TCHUNK  74            // ceil(2046/28)
#define NTILE   27            // ceil(81 warps / 3 warps-per-block)
#define TILE_W  384           // padded tile width (bytes); block covers 376 stream cols
#define WARPS_PB 3
#define THREADS_PB 96
#define EXT_W   10512         // D + 512, circularly extended & shifted by 4
#define PART_STRIDE 10048

// ---------------- scratch (static device globals; no allocation) ----------------
__device__ unsigned char g_lwext[LVL * EXT_W];     // ext[row][j] = (LW[row][(j-4) mod D] > 0)
__device__ unsigned char g_keys01[4 * D_DIM];      // (keys_hv > 0)
__device__ int           g_idxp[T_STEPS];          // 4 packed 8-bit level indices per t
__device__ int           g_partial[NCHUNK * PART_STRIDE];
__device__ float         g_comb[D_DIM];

__constant__ int c_CF[29] = {547,548,549,551,554,556,557,558,559,560,561,562,563,565,
                             566,567,570,576,580,581,582,583,584,585,588,593,598,599,600};

// ---------------- prep kernels ----------------
__device__ __forceinline__ int level_of(float x) {
    x = fminf(fmaxf(x, 0.0f), 1.0f);
    float r = rintf(x * 99.0f);          // round-half-to-even, matches jnp.round
    int i = (int)r;
    i = i < 0 ? 0 : (i > 99 ? 99 : i);
    return i;
}

__global__ void k_prep_idx(const float* __restrict__ signals) {
    int t = blockIdx.x * blockDim.x + threadIdx.x;
    if (t >= T_STEPS) return;
    float4 sg = ((const float4*)signals)[t];
    int i0 = level_of(sg.x), i1 = level_of(sg.y), i2 = level_of(sg.z), i3 = level_of(sg.w);
    g_idxp[t] = i0 | (i1 << 8) | (i2 << 16) | (i3 << 24);
}

__global__ void k_prep_lw(const float* __restrict__ lw) {
    int i = blockIdx.x * blockDim.x + threadIdx.x;
    if (i >= LVL * EXT_W) return;
    int row = i / EXT_W;
    int col = i - row * EXT_W;
    int src = col - 4;
    if (src < 0) src += D_DIM;
    else if (src >= D_DIM) src -= D_DIM;
    g_lwext[i] = (lw[row * D_DIM + src] > 0.0f) ? 1 : 0;
}

__global__ void k_prep_keys(const float* __restrict__ keys) {
    int i = blockIdx.x * blockDim.x + threadIdx.x;
    if (i >= 4 * D_DIM) return;
    g_keys01[i] = (keys[i] > 0.0f) ? 1 : 0;
}

// ---------------- comb kernel: warp per d ----------------
__global__ void k_comb(const float* __restrict__ feat,
                       const float* __restrict__ feat_w,
                       const float* __restrict__ feat_b,
                       const float* __restrict__ mfcc_w,
                       const float* __restrict__ mfcc_b) {
    int lane = threadIdx.x & 31;
    int wib  = threadIdx.x >> 5;
    int d = blockIdx.x * 8 + wib;
    if (d >= D_DIM) return;

    // 6 MFCC sinusoid kernels: mproj_k = sum_f mfcc_w[k][d][f] * feat[k*91+f]
    float mfcc_hv = 1.0f;
    #pragma unroll
    for (int k = 0; k < 6; k++) {
        const float* wrow = mfcc_w + ((size_t)k * D_DIM + (size_t)d) * 91;
        const float* frow = feat + k * 91;
        float p = 0.0f;
        for (int f = lane; f < 91; f += 32) p += wrow[f] * frow[f];
        #pragma unroll
        for (int o = 16; o > 0; o >>= 1) p += __shfl_xor_sync(0xffffffffu, p, o);
        float b = mfcc_b[k * D_DIM + d];
        mfcc_hv *= cosf(p + b) * sinf(p);
    }

    __shared__ float fhv_sm[8][32];
    if (lane < 29) {
        float sel  = feat[c_CF[lane] - 1];
        float wv   = feat_w[lane * D_DIM + d];
        float bv   = feat_b[lane * D_DIM + d];
        float proj = sel * wv;
        fhv_sm[wib][lane] = cosf(proj + bv) * sinf(proj);
    }
    __syncwarp();
    if (lane == 0) {
        const float* h = fhv_sm[wib];
        float comb =
              h[0]  * h[8]  * h[13]
            + h[1]  * h[9]  * h[14]
            + h[2]  * h[10] * h[15]
            + h[3]  * h[4]
            + h[5] * h[7] * h[22] * h[6] * h[23] * h[19] * h[18]
                   * h[20] * h[21] * h[26] * h[28] * h[27]
            + h[11] + h[12]
            + h[16] * h[24]
            + h[17] + h[25]
            + mfcc_hv;
        g_comb[d] = comb;
    }
}

// ---------------- main n-gram kernel ----------------
// Bytewise sign algebra: b01 = (x>0); lw*key = 1-2*(bl^bk); per_t = 4-2*s, s=sum_c xor.
// With u = s-2, per_t = -2u, so ngram term = -8 * uA*uB*uC. All exact integers.
__device__ __forceinline__ void load_u(const unsigned char* lw_sm, const int* idx_sm,
                                       int i, int locOff, const int* kw, int* u) {
    int iq = idx_sm[i];
    int x0 = *(const int*)(lw_sm + ((iq      ) & 0xFF) * TILE_W + locOff) ^ kw[0];
    int x1 = *(const int*)(lw_sm + ((iq >> 8 ) & 0xFF) * TILE_W + locOff) ^ kw[1];
    int x2 = *(const int*)(lw_sm + ((iq >> 16) & 0xFF) * TILE_W + locOff) ^ kw[2];
    int x3 = *(const int*)(lw_sm + ((iq >> 24)       ) * TILE_W + locOff) ^ kw[3];
    int sp = x0 + x1 + x2 + x3;       // bytewise sums, each <= 4, no carries
    u[0] = ( sp        & 0xFF) - 2;
    u[1] = ((sp >> 8 ) & 0xFF) - 2;
    u[2] = ((sp >> 16) & 0xFF) - 2;
    u[3] = ( sp >> 24        ) - 2;
}

__global__ __launch_bounds__(THREADS_PB) void k_main() {
    __shared__ unsigned char lw_sm[LVL * TILE_W];
    __shared__ int idx_sm[TCHUNK + 2];

    int tb = blockIdx.x;     // column tile
    int s  = blockIdx.y;     // t-chunk
    int tid = threadIdx.x;
    int w = tid >> 5, l = tid & 31;

    // Load level tile (int8, circularly extended so contiguous & word-aligned)
    int base = 372 * tb;     // into ext array (already shifted by 4)
    {
        int* dst = (int*)lw_sm;
        for (int i = tid; i < LVL * (TILE_W / 4); i += THREADS_PB) {
            int row = i / (TILE_W / 4);
            int wj  = i - row * (TILE_W / 4);
            dst[i] = *(const int*)(g_lwext + row * EXT_W + base + 4 * wj);
        }
    }
    int ts = s * TCHUNK;
    int te = ts + TCHUNK; if (te > TERMS) te = TERMS;
    int nt = te - ts;                      // #terms this chunk (>= 1)
    for (int i = tid; i < nt + 2; i += THREADS_PB) idx_sm[i] = g_idxp[ts + i];
    __syncthreads();

    int g = WARPS_PB * tb + w;             // global warp id (column group)
    // this lane's 4 stream columns start at real col (124g - 4 + 4l) mod D
    int v = 124 * g - 4 + 4 * l;
    if (v < 0) v += D_DIM;
    if (v >= D_DIM) v -= D_DIM;
    int kw[4];
    #pragma unroll
    for (int c = 0; c < 4; c++) kw[c] = *(const int*)(g_keys01 + c * D_DIM + v);

    int locOff = 124 * w + 4 * l;          // byte offset of stream j=0 within tile row

    int p1[4], p2[4], cur[4];
    int acc[4] = {0, 0, 0, 0};
    load_u(lw_sm, idx_sm, 0, locOff, kw, p2);   // u(ts)
    load_u(lw_sm, idx_sm, 1, locOff, kw, p1);   // u(ts+1)

    #pragma unroll 2
    for (int i = 2; i < nt + 2; i++) {
        load_u(lw_sm, idx_sm, i, locOff, kw, cur);   // u(ts+i)
        // emit term(ts+i-2): u_{c-2}(t) * u_{c-1}(t+1) * u_c(t+2)
        int a0 = __shfl_up_sync(0xffffffffu, p2[2], 1);
        int a1 = __shfl_up_sync(0xffffffffu, p2[3], 1);
        int b0 = __shfl_up_sync(0xffffffffu, p1[3], 1);
        acc[0] += a0    * b0    * cur[0];
        acc[1] += a1    * p1[0] * cur[1];
        acc[2] += p2[0] * p1[1] * cur[2];
        acc[3] += p2[1] * p1[2] * cur[3];
        p2[0] = p1[0]; p2[1] = p1[1]; p2[2] = p1[2]; p2[3] = p1[3];
        p1[0] = cur[0]; p1[1] = cur[1]; p1[2] = cur[2]; p1[3] = cur[3];
    }

    if (l >= 1) {                           // lane 0 is halo-only
        int obase = 124 * g + 4 * (l - 1);
        int* prow = g_partial + s * PART_STRIDE;
        #pragma unroll
        for (int j = 0; j < 4; j++) {
            int oc = obase + j;
            if (oc < D_DIM) prow[oc] = acc[j];
        }
    }
}

// ---------------- final reduce + quantize ----------------
__global__ void k_final(float* __restrict__ out) {
    int d = blockIdx.x * blockDim.x + threadIdx.x;
    if (d >= D_DIM) return;
    int sum = 0;
    #pragma unroll
    for (int c = 0; c < NCHUNK; c++) sum += g_partial[c * PART_STRIDE + d];
    float sample = -8.0f * (float)sum;      // exact: |.| < 2^24
    float x = sample * g_comb[d];
    out[d] = (x > 0.0f) ? 1.0f : -1.0f;
}

// ---------------- launch ----------------
extern "C" void kernel_launch(void* const* d_in, const int* in_sizes, int n_in,
                              void* d_out, int out_size) {
    const float* signals = (const float*)d_in[0];
    const float* feat    = (const float*)d_in[1];
    const float* keys_hv = (const float*)d_in[2];
    const float* lw      = (const float*)d_in[3];
    const float* feat_w  = (const float*)d_in[4];
    const float* feat_b  = (const float*)d_in[5];
    const float* mfcc_w  = (const float*)d_in[6];
    const float* mfcc_b  = (const float*)d_in[7];
    float* out = (float*)d_out;

    k_prep_idx <<<(T_STEPS + 127) / 128, 128>>>(signals);
    k_prep_keys<<<(4 * D_DIM + 255) / 256, 256>>>(keys_hv);
    k_prep_lw  <<<(LVL * EXT_W + 255) / 256, 256>>>(lw);
    k_comb     <<<(D_DIM + 7) / 8, 256>>>(feat, feat_w, feat_b, mfcc_w, mfcc_b);
    k_main     <<<dim3(NTILE, NCHUNK), THREADS_PB>>>();
    k_final    <<<(D_DIM + 255) / 256, 256>>>(out);
}